// round 6
// baseline (speedup 1.0000x reference)
#include <cuda_runtime.h>
#include <cuda_bf16.h>
#include <math.h>

// Problem constants
#define BB 1024   // batch
#define II 256    // in features
#define OO 256    // out features
#define KK 128    // knots

// Spline-kernel tiling
#define OT 32               // o per CTA (one per lane)
#define NICHUNK 16          // i-chunks in grid
#define IPC (II / NICHUNK)  // 16 i per chunk
#define PSTR 129            // ptile row stride in float2 (odd -> conflict-free gathers)

// Dynamic smem layout (bytes)
#define PTILE_BYTES (OT * PSTR * 8)          // 33024
#define MTILE_OFF   PTILE_BYTES              // 33024
#define MTILE_BYTES (BB * 16)                // 16384
#define WSTILE_OFF  (MTILE_OFF + MTILE_BYTES)
#define WSTILE_BYTES (OT * 17 * 8)           // 4352
#define SMEM_TOTAL  (WSTILE_OFF + WSTILE_BYTES)

// Scratch: meta[i][b] = {frac, (l*8) byte-offset as bits, silu, unused}
__device__ float4 g_meta[II * BB];   // 4 MB

// ---------------------------------------------------------------------------
// Kernel 1: per-element activation / knot prep, written transposed [i][b]
// ---------------------------------------------------------------------------
__global__ void kan_prep(const float* __restrict__ x) {
    __shared__ float4 sm[32][33];
    int i = blockIdx.x * 32 + threadIdx.x;
    int b = blockIdx.y * 32 + threadIdx.y;

    float xv = x[b * II + i];
    float p = tanhf(xv);                         // accurate tanh (63.5x error amplification downstream)
    float sig = 1.0f / (1.0f + __expf(-p));
    float silu = p * sig;
    float c = fminf(fmaxf(p, -1.0f), 1.0f);
    float scaled = (c + 1.0f) * 63.5f;           // (c - DMIN)/step, step = 2/127
    int l = (int)scaled;
    if (l > 126) l = 126;                        // entry l stores {c[l], c[l+1]-c[l]}; l=126,f=1 -> c[127] exact
    float frac = scaled - (float)l;

    sm[threadIdx.y][threadIdx.x] = make_float4(frac, __int_as_float(l * 8), silu, 0.0f);
    __syncthreads();

    int i2 = blockIdx.x * 32 + threadIdx.y;
    int b2 = blockIdx.y * 32 + threadIdx.x;
    g_meta[i2 * BB + b2] = sm[threadIdx.x][threadIdx.y];  // coalesced over b2
}

// ---------------------------------------------------------------------------
// Kernel 2: out[b,o] = bias[o]  (out arrives poisoned; atomics need real init)
// ---------------------------------------------------------------------------
__global__ void kan_init(const float* __restrict__ bias, float* __restrict__ out) {
    int idx = blockIdx.x * blockDim.x + threadIdx.x;
    out[idx] = bias[idx & (OO - 1)];
}

// ---------------------------------------------------------------------------
// Kernel 3: spline gather + base GEMM, register-prefetch pipelined.
// grid = (NICHUNK, 1, OO/OT) = 128 CTAs (<=1/SM), block = 1024 (32 warps).
// Warp w owns b in [32w, 32w+32); lane = o within the 32-o tile.
// ---------------------------------------------------------------------------
__global__ __launch_bounds__(1024, 1)
void kan_spline(const float* __restrict__ coeff,   // [O][I][K]
                const float* __restrict__ scale,   // [O][I]
                const float* __restrict__ bw,      // [O][I]
                float* __restrict__ out) {         // [B][O]
    extern __shared__ char smem_raw[];
    float2* ptile  = (float2*)smem_raw;                       // [OT][PSTR] {c[k], c[k+1]-c[k]}
    float4* mtile  = (float4*)(smem_raw + MTILE_OFF);         // [1024] meta
    float2* wstile = (float2*)(smem_raw + WSTILE_OFF);        // [OT][17] {w, sc}

    const int tid  = threadIdx.x;
    const int lane = tid & 31;
    const int warp = tid >> 5;
    const int o0 = blockIdx.z * OT;
    const int i0 = blockIdx.x * IPC;

    // preload {base-weight, spline-scale} tile: [o][ii]
    if (tid < OT * IPC) {
        int o  = tid >> 4;      // 0..31
        int ii = tid & 15;      // 0..15
        size_t gi = (size_t)(o0 + o) * II + i0 + ii;
        wstile[o * 17 + ii] = make_float2(bw[gi], scale[gi]);
    }

    float acc[32];
#pragma unroll
    for (int j = 0; j < 32; j++) acc[j] = 0.0f;

    // register prefetch for ii = 0 (warp w loads coeff row o0+w, lane = float4 segment)
    const float4* crow0 = (const float4*)(coeff + ((size_t)(o0 + warp) * II + i0) * KK);
    float4 creg = crow0[lane];
    float4 mreg = g_meta[(size_t)i0 * BB + tid];

    const char* myrow = (const char*)(ptile + lane * PSTR);   // gather base for this lane's o

    for (int ii = 0; ii < IPC; ii++) {
        __syncthreads();   // all readers of previous tile done

        // store current tile: pair-difference entries {c[k], c[k+1]-c[k]}
        {
            float nxt = __shfl_down_sync(0xffffffffu, creg.x, 1);  // next segment's first elem
            float2* prow = ptile + warp * PSTR + lane * 4;
            prow[0] = make_float2(creg.x, creg.y - creg.x);
            prow[1] = make_float2(creg.y, creg.z - creg.y);
            prow[2] = make_float2(creg.z, creg.w - creg.z);
            prow[3] = make_float2(creg.w, nxt - creg.w);           // k=127 diff unused (l<=126)
            mtile[tid] = mreg;
        }
        __syncthreads();   // tile ready

        // prefetch next iteration's tile into registers (latency hidden by body)
        if (ii + 1 < IPC) {
            const float4* crow = (const float4*)(coeff + ((size_t)(o0 + warp) * II + i0 + ii + 1) * KK);
            creg = crow[lane];
            mreg = g_meta[(size_t)(i0 + ii + 1) * BB + tid];
        }

        float2 ws = wstile[lane * 17 + ii];   // {w[o,i], sc[o,i]}

#pragma unroll
        for (int bb = 0; bb < 32; bb++) {
            float4 m = mtile[warp * 32 + bb];                       // broadcast, 1 phase
            float2 cd = *(const float2*)(myrow + __float_as_int(m.y));  // LDS.64, conflict-free
            float v = fmaf(m.x, cd.y, cd.x);                        // lerp: cl + f*(cr-cl)
            float a = acc[bb];
            a = fmaf(ws.y, v, a);                                   // spline * scale
            a = fmaf(m.z, ws.x, a);                                 // base: silu * W[o,i]
            acc[bb] = a;
        }
    }

    float* op = out + (size_t)(warp * 32) * OO + o0 + lane;
#pragma unroll
    for (int bb = 0; bb < 32; bb++)
        atomicAdd(op + (size_t)bb * OO, acc[bb]);
}

// ---------------------------------------------------------------------------
// Launch
// ---------------------------------------------------------------------------
extern "C" void kernel_launch(void* const* d_in, const int* in_sizes, int n_in,
                              void* d_out, int out_size) {
    const float* x     = (const float*)d_in[0];  // [B][I]
    const float* bw    = (const float*)d_in[1];  // [O][I]
    const float* coeff = (const float*)d_in[2];  // [O][I][K]
    const float* scale = (const float*)d_in[3];  // [O][I]
    const float* bias  = (const float*)d_in[4];  // [O]
    float* out = (float*)d_out;                  // [B][O]

    static bool attr_set = false;
    if (!attr_set) {
        cudaFuncSetAttribute(kan_spline, cudaFuncAttributeMaxDynamicSharedMemorySize, SMEM_TOTAL);
        attr_set = true;
    }

    kan_prep<<<dim3(II / 32, BB / 32), dim3(32, 32)>>>(x);
    kan_init<<<(BB * OO) / 256, 256>>>(bias, out);
    kan_spline<<<dim3(NICHUNK, 1, OO / OT), 1024, SMEM_TOTAL>>>(coeff, scale, bw, out);
}